// round 5
// baseline (speedup 1.0000x reference)
#include <cuda_runtime.h>
#include <math.h>

// Problem constants
#define B_      4
#define NQ      2048
#define NK      1024
#define DQ      512
#define DC      768
#define HEADS   8
#define DIMH    64
#define INNER   512           // HEADS*DIMH
#define SCALE   0.125f        // 1/sqrt(64)

// -------- device scratch (no allocations allowed) --------
__device__ float g_q [B_ * NQ * INNER];   // 16 MB
__device__ float g_k [B_ * NK * INNER];   // 8 MB
__device__ float g_v [B_ * NK * INNER];   // 8 MB
__device__ float g_ao[B_ * NQ * INNER];   // 16 MB

// ============================================================
// Generic tiled SGEMM: C[M,N] = A[M,K] @ B[K,N] (+ bias[N])
// BM=BN=64, BK=16, 256 threads, 4x4 per thread.
// M,N,K all multiples of 64/16 for this problem -> no guards.
// ============================================================
__global__ __launch_bounds__(256)
void sgemm_kernel(const float* __restrict__ A, const float* __restrict__ Bm,
                  float* __restrict__ C, int M, int N, int K,
                  const float* __restrict__ bias)
{
    __shared__ float As[16][64];   // transposed A tile: As[k][m]
    __shared__ float Bs[16][64];   // Bs[k][n]

    const int tid = threadIdx.x;
    const int tx  = tid & 15;          // 0..15 -> n
    const int ty  = tid >> 4;          // 0..15 -> m
    const int bm  = blockIdx.y * 64;
    const int bn  = blockIdx.x * 64;

    float acc[4][4];
#pragma unroll
    for (int i = 0; i < 4; i++)
#pragma unroll
        for (int j = 0; j < 4; j++) acc[i][j] = 0.f;

    const int nKt = K >> 4;
    // A-load mapping: row = tid/4 (0..63), kcol0 = (tid%4)*4
    const int ar  = tid >> 2;
    const int ac0 = (tid & 3) * 4;
    // B-load mapping: krow = tid/16, ncol0 = (tid%16)*4
    const int br  = tid >> 4;
    const int bc0 = (tid & 15) * 4;

    for (int kt = 0; kt < nKt; kt++) {
        // load A tile (64 x 16), store transposed
        {
            const float4 av = *reinterpret_cast<const float4*>(
                &A[(size_t)(bm + ar) * K + kt * 16 + ac0]);
            As[ac0 + 0][ar] = av.x;
            As[ac0 + 1][ar] = av.y;
            As[ac0 + 2][ar] = av.z;
            As[ac0 + 3][ar] = av.w;
        }
        // load B tile (16 x 64)
        {
            const float4 bv = *reinterpret_cast<const float4*>(
                &Bm[(size_t)(kt * 16 + br) * N + bn + bc0]);
            *reinterpret_cast<float4*>(&Bs[br][bc0]) = bv;
        }
        __syncthreads();

#pragma unroll
        for (int k = 0; k < 16; k++) {
            float a0 = As[k][ty * 4 + 0];
            float a1 = As[k][ty * 4 + 1];
            float a2 = As[k][ty * 4 + 2];
            float a3 = As[k][ty * 4 + 3];
            float4 bv = *reinterpret_cast<const float4*>(&Bs[k][tx * 4]);
            acc[0][0] += a0 * bv.x; acc[0][1] += a0 * bv.y; acc[0][2] += a0 * bv.z; acc[0][3] += a0 * bv.w;
            acc[1][0] += a1 * bv.x; acc[1][1] += a1 * bv.y; acc[1][2] += a1 * bv.z; acc[1][3] += a1 * bv.w;
            acc[2][0] += a2 * bv.x; acc[2][1] += a2 * bv.y; acc[2][2] += a2 * bv.z; acc[2][3] += a2 * bv.w;
            acc[3][0] += a3 * bv.x; acc[3][1] += a3 * bv.y; acc[3][2] += a3 * bv.z; acc[3][3] += a3 * bv.w;
        }
        __syncthreads();
    }

#pragma unroll
    for (int i = 0; i < 4; i++) {
        const int row = bm + ty * 4 + i;
        const int col = bn + tx * 4;
        float4 out;
        out.x = acc[i][0]; out.y = acc[i][1]; out.z = acc[i][2]; out.w = acc[i][3];
        if (bias) {
            out.x += bias[col + 0];
            out.y += bias[col + 1];
            out.z += bias[col + 2];
            out.w += bias[col + 3];
        }
        *reinterpret_cast<float4*>(&C[(size_t)row * N + col]) = out;
    }
}

// ============================================================
// Flash attention (fp32): one thread owns one query row.
// Block = 128 threads = 128 query rows for one (b,h).
// K/V staged in shared as 32-key tiles of float4[16] (d=64).
// ============================================================
__global__ __launch_bounds__(128)
void attn_kernel(const float* __restrict__ q, const float* __restrict__ k,
                 const float* __restrict__ v, float* __restrict__ out)
{
    const int b   = blockIdx.z;
    const int h   = blockIdx.y;
    const int row = blockIdx.x * 128 + threadIdx.x;

    __shared__ float4 Ks[32][16];
    __shared__ float4 Vs[32][16];

    // load q row into registers
    float4 qr[16];
    {
        const float4* qp = reinterpret_cast<const float4*>(
            &q[((size_t)(b * NQ + row) * INNER) + h * DIMH]);
#pragma unroll
        for (int d = 0; d < 16; d++) qr[d] = qp[d];
    }

    float m = -INFINITY;
    float l = 0.f;
    float4 acc[16];
#pragma unroll
    for (int d = 0; d < 16; d++) acc[d] = make_float4(0.f, 0.f, 0.f, 0.f);

    const int nTiles = NK / 32;
    for (int kt = 0; kt < nTiles; kt++) {
        __syncthreads();
        // cooperative load of 32 keys + 32 values (512 float4 each)
#pragma unroll
        for (int t = 0; t < 4; t++) {
            const int e    = threadIdx.x + t * 128;   // 0..511
            const int jrow = e >> 4;
            const int d4   = e & 15;
            const size_t gk = ((size_t)(b * NK + kt * 32 + jrow) * INNER) + h * DIMH;
            Ks[jrow][d4] = reinterpret_cast<const float4*>(&k[gk])[d4];
            Vs[jrow][d4] = reinterpret_cast<const float4*>(&v[gk])[d4];
        }
        __syncthreads();

        // scores
        float s[32];
#pragma unroll
        for (int j = 0; j < 32; j++) {
            float acc_s = 0.f;
#pragma unroll
            for (int d = 0; d < 16; d++) {
                const float4 kk = Ks[j][d];
                acc_s += qr[d].x * kk.x + qr[d].y * kk.y
                       + qr[d].z * kk.z + qr[d].w * kk.w;
            }
            s[j] = acc_s * SCALE;
        }

        // online softmax
        float tmax = s[0];
#pragma unroll
        for (int j = 1; j < 32; j++) tmax = fmaxf(tmax, s[j]);
        const float m_new = fmaxf(m, tmax);
        const float corr  = __expf(m - m_new);
        l *= corr;
#pragma unroll
        for (int d = 0; d < 16; d++) {
            acc[d].x *= corr; acc[d].y *= corr;
            acc[d].z *= corr; acc[d].w *= corr;
        }
        m = m_new;

#pragma unroll
        for (int j = 0; j < 32; j++) {
            const float p = __expf(s[j] - m);
            l += p;
#pragma unroll
            for (int d = 0; d < 16; d++) {
                const float4 vv = Vs[j][d];
                acc[d].x += p * vv.x; acc[d].y += p * vv.y;
                acc[d].z += p * vv.z; acc[d].w += p * vv.w;
            }
        }
    }

    // write normalized output row
    const float inv = 1.f / l;
    float4* op = reinterpret_cast<float4*>(
        &out[((size_t)(b * NQ + row) * INNER) + h * DIMH]);
#pragma unroll
    for (int d = 0; d < 16; d++) {
        float4 o;
        o.x = acc[d].x * inv; o.y = acc[d].y * inv;
        o.z = acc[d].z * inv; o.w = acc[d].w * inv;
        op[d] = o;
    }
}

// ============================================================
extern "C" void kernel_launch(void* const* d_in, const int* in_sizes, int n_in,
                              void* d_out, int out_size)
{
    const float* x   = (const float*)d_in[0];   // [4,2048,512]
    const float* ctx = (const float*)d_in[1];   // [4,1024,768]
    const float* Wq  = (const float*)d_in[2];   // [512,512]
    const float* Wk  = (const float*)d_in[3];   // [768,512]
    const float* Wv  = (const float*)d_in[4];   // [768,512]
    const float* Wo  = (const float*)d_in[5];   // [512,512]
    const float* bo  = (const float*)d_in[6];   // [512]
    float* out       = (float*)d_out;           // [4,2048,512]

    float *q, *k, *v, *ao;
    cudaGetSymbolAddress((void**)&q,  g_q);
    cudaGetSymbolAddress((void**)&k,  g_k);
    cudaGetSymbolAddress((void**)&v,  g_v);
    cudaGetSymbolAddress((void**)&ao, g_ao);

    // Q = x @ Wq : [8192,512] = [8192,512]@[512,512]
    {
        dim3 grid(INNER / 64, (B_ * NQ) / 64);
        sgemm_kernel<<<grid, 256>>>(x, Wq, q, B_ * NQ, INNER, DQ, nullptr);
    }
    // K = ctx @ Wk : [4096,512] = [4096,768]@[768,512]
    {
        dim3 grid(INNER / 64, (B_ * NK) / 64);
        sgemm_kernel<<<grid, 256>>>(ctx, Wk, k, B_ * NK, INNER, DC, nullptr);
    }
    // V = ctx @ Wv
    {
        dim3 grid(INNER / 64, (B_ * NK) / 64);
        sgemm_kernel<<<grid, 256>>>(ctx, Wv, v, B_ * NK, INNER, DC, nullptr);
    }
    // attention
    {
        dim3 grid(NQ / 128, HEADS, B_);
        attn_kernel<<<grid, 128>>>(q, k, v, ao);
    }
    // out = ao @ Wo + bo
    {
        dim3 grid(DQ / 64, (B_ * NQ) / 64);
        sgemm_kernel<<<grid, 256>>>(ao, Wo, out, B_ * NQ, DQ, INNER, bo);
    }
}

// round 7
// speedup vs baseline: 1.3297x; 1.3297x over previous
#include <cuda_runtime.h>
#include <cuda_bf16.h>
#include <math.h>
#include <stdint.h>

#define B_      4
#define NQ      2048
#define NK      1024
#define DQ      512
#define DC      768
#define HEADS   8
#define DIMH    64
#define INNER   512
#define SCALE   0.125f

__device__ float g_q [B_ * NQ * INNER];
__device__ float g_k [B_ * NK * INNER];
__device__ float g_v [B_ * NK * INNER];
__device__ float g_ao[B_ * NQ * INNER];

#define WT_Q 0
#define WT_K (512*512)
#define WT_V (512*512 + 768*512)
#define WT_O (512*512 + 2*768*512)
#define WT_TOTAL (2*512*512 + 2*768*512)
__device__ __nv_bfloat16 g_wth[WT_TOTAL];
__device__ __nv_bfloat16 g_wtl[WT_TOTAL];

// ---------------- helpers ----------------
__device__ __forceinline__ uint32_t smem_u32(const void* p) {
    uint32_t a;
    asm("{ .reg .u64 t; cvta.to.shared.u64 t, %1; cvt.u32.u64 %0, t; }" : "=r"(a) : "l"(p));
    return a;
}
__device__ __forceinline__ uint32_t sw128(uint32_t o) { return o ^ ((o >> 3) & 0x70); }

__device__ __forceinline__ void ldsm_x4(uint32_t* r, uint32_t addr) {
    asm volatile("ldmatrix.sync.aligned.m8n8.x4.shared.b16 {%0,%1,%2,%3}, [%4];"
                 : "=r"(r[0]), "=r"(r[1]), "=r"(r[2]), "=r"(r[3]) : "r"(addr));
}
__device__ __forceinline__ void ldsm_x2(uint32_t* r, uint32_t addr) {
    asm volatile("ldmatrix.sync.aligned.m8n8.x2.shared.b16 {%0,%1}, [%2];"
                 : "=r"(r[0]), "=r"(r[1]) : "r"(addr));
}
__device__ __forceinline__ void mma16816(float* c, const uint32_t* a, const uint32_t* b) {
    asm volatile("mma.sync.aligned.m16n8k16.row.col.f32.bf16.bf16.f32 "
                 "{%0,%1,%2,%3}, {%4,%5,%6,%7}, {%8,%9}, {%0,%1,%2,%3};"
                 : "+f"(c[0]), "+f"(c[1]), "+f"(c[2]), "+f"(c[3])
                 : "r"(a[0]), "r"(a[1]), "r"(a[2]), "r"(a[3]), "r"(b[0]), "r"(b[1]));
}

// ------------- weight transpose + hi/lo split: W[K][N] f32 -> [N][K] bf16 -------------
__global__ __launch_bounds__(256)
void transpose_split(const float* __restrict__ W, __nv_bfloat16* __restrict__ Th,
                     __nv_bfloat16* __restrict__ Tl, int K, int N)
{
    __shared__ float tile[32][33];
    const int k0 = blockIdx.x * 32, n0 = blockIdx.y * 32;
    const int tx = threadIdx.x & 31, ty = threadIdx.x >> 5;
#pragma unroll
    for (int r = 0; r < 4; r++)
        tile[ty + r * 8][tx] = W[(size_t)(k0 + ty + r * 8) * N + n0 + tx];
    __syncthreads();
#pragma unroll
    for (int r = 0; r < 4; r++) {
        int n = n0 + ty + r * 8, k = k0 + tx;
        float v = tile[tx][ty + r * 8];
        uint32_t b = __float_as_uint(v);
        unsigned short hs = (unsigned short)(b >> 16);
        float hi = __uint_as_float(b & 0xFFFF0000u);
        __nv_bfloat16 h; reinterpret_cast<unsigned short&>(h) = hs;
        Th[(size_t)n * K + k] = h;
        Tl[(size_t)n * K + k] = __float2bfloat16(v - hi);
    }
}

// ------------- HMMA split-bf16 GEMM: C[M,N]=A[M,K]@W[K,N] (+bias) -------------
// B pre-transposed/split [N][K] bf16. Tile 128x128, K-chunk 64 (SW128 128B rows).
// 8 warps: warp (w&3) -> M 32-slab, (w>>2) -> N 64-slab.
#define TC_SMEM 65536
#define AHI 0
#define ALO 16384
#define BHI 32768
#define BLO 49152

__global__ __launch_bounds__(256)
void tc_gemm(const float* __restrict__ A, const __nv_bfloat16* __restrict__ Bh,
             const __nv_bfloat16* __restrict__ Bl, float* __restrict__ C,
             int M, int N, int K, const float* __restrict__ bias)
{
    extern __shared__ char tb[];
    const uint32_t sbase = smem_u32(tb);
    const int tid = threadIdx.x, wid = tid >> 5, lane = tid & 31;
    const int m0 = blockIdx.y * 128, n0 = blockIdx.x * 128;
    const int wm = (wid & 3) * 32, wn = (wid >> 2) * 64;

    float acc[2][8][4];
#pragma unroll
    for (int mt = 0; mt < 2; mt++)
#pragma unroll
        for (int nt = 0; nt < 8; nt++)
#pragma unroll
            for (int i = 0; i < 4; i++) acc[mt][nt][i] = 0.f;

    const int r8  = lane & 7;
    const int q4  = lane >> 3;          // 0..3 for ldsm x4
    const int l16 = lane & 15;
    const int q2  = l16 >> 3;           // 0..1 for ldsm x2

    const int nchunks = K >> 6;
    for (int kt = 0; kt < nchunks; kt++) {
        const int kb = kt << 6;
        // ---- A: 128x64 f32 -> hi/lo bf16 into SW128 smem ----
#pragma unroll
        for (int t = 0; t < 8; t++) {
            int idx = tid + t * 256;             // 0..2047
            int row = idx >> 4, c4 = (idx & 15) << 2;
            float4 v = *reinterpret_cast<const float4*>(&A[(size_t)(m0 + row) * K + kb + c4]);
            uint32_t bx = __float_as_uint(v.x), by = __float_as_uint(v.y),
                     bz = __float_as_uint(v.z), bw = __float_as_uint(v.w);
            uint32_t h01 = (bx >> 16) | (by & 0xFFFF0000u);
            uint32_t h23 = (bz >> 16) | (bw & 0xFFFF0000u);
            __nv_bfloat162 l01b = __floats2bfloat162_rn(
                v.x - __uint_as_float(bx & 0xFFFF0000u), v.y - __uint_as_float(by & 0xFFFF0000u));
            __nv_bfloat162 l23b = __floats2bfloat162_rn(
                v.z - __uint_as_float(bz & 0xFFFF0000u), v.w - __uint_as_float(bw & 0xFFFF0000u));
            uint32_t off = sw128((uint32_t)(row * 128 + (c4 << 1)));
            *reinterpret_cast<uint64_t*>(tb + AHI + off) = ((uint64_t)h23 << 32) | h01;
            *reinterpret_cast<uint64_t*>(tb + ALO + off) =
                ((uint64_t)reinterpret_cast<uint32_t&>(l23b) << 32) | reinterpret_cast<uint32_t&>(l01b);
        }
        // ---- B: 128 rows x 64 bf16 (pre-split [N][K]) -> SW128 smem ----
#pragma unroll
        for (int t = 0; t < 4; t++) {
            int idx = tid + t * 256;             // 0..1023
            int row = idx >> 3, c8 = (idx & 7) << 3;
            size_t g = (size_t)(n0 + row) * K + kb + c8;
            uint32_t off = sw128((uint32_t)(row * 128 + (c8 << 1)));
            *reinterpret_cast<uint4*>(tb + BHI + off) = *reinterpret_cast<const uint4*>(&Bh[g]);
            *reinterpret_cast<uint4*>(tb + BLO + off) = *reinterpret_cast<const uint4*>(&Bl[g]);
        }
        __syncthreads();

        // ---- compute: 4 k16 steps ----
#pragma unroll
        for (int ks = 0; ks < 4; ks++) {
            const int k0 = ks * 16;
            uint32_t ah[2][4], al[2][4];
#pragma unroll
            for (int mt = 0; mt < 2; mt++) {
                int am = wm + mt * 16 + r8 + (q4 & 1) * 8;
                int ak = k0 + (q4 >> 1) * 8;
                uint32_t o = sw128((uint32_t)(am * 128 + ak * 2));
                ldsm_x4(ah[mt], sbase + AHI + o);
                ldsm_x4(al[mt], sbase + ALO + o);
            }
#pragma unroll
            for (int nt = 0; nt < 8; nt++) {
                int bn = wn + nt * 8 + r8;
                int bk = k0 + q2 * 8;
                uint32_t o = sw128((uint32_t)(bn * 128 + bk * 2));
                uint32_t bh[2], bl[2];
                ldsm_x2(bh, sbase + BHI + o);
                ldsm_x2(bl, sbase + BLO + o);
#pragma unroll
                for (int mt = 0; mt < 2; mt++) {
                    mma16816(acc[mt][nt], ah[mt], bh);
                    mma16816(acc[mt][nt], al[mt], bh);
                    mma16816(acc[mt][nt], ah[mt], bl);
                }
            }
        }
        __syncthreads();
    }

    // ---- epilogue: c-frag layout: rows t/4, t/4+8; cols 2*(t%4)+{0,1} ----
    const int cr = lane >> 2, cc = (lane & 3) * 2;
#pragma unroll
    for (int mt = 0; mt < 2; mt++) {
#pragma unroll
        for (int nt = 0; nt < 8; nt++) {
            int col = n0 + wn + nt * 8 + cc;
            float b0 = 0.f, b1 = 0.f;
            if (bias) { b0 = bias[col]; b1 = bias[col + 1]; }
            int row = m0 + wm + mt * 16 + cr;
            float2 v0 = make_float2(acc[mt][nt][0] + b0, acc[mt][nt][1] + b1);
            float2 v1 = make_float2(acc[mt][nt][2] + b0, acc[mt][nt][3] + b1);
            *reinterpret_cast<float2*>(&C[(size_t)row * N + col]) = v0;
            *reinterpret_cast<float2*>(&C[(size_t)(row + 8) * N + col]) = v1;
        }
    }
}

// ------------- attention (fp32 baseline, unchanged) -------------
__global__ __launch_bounds__(128)
void attn_kernel(const float* __restrict__ q, const float* __restrict__ k,
                 const float* __restrict__ v, float* __restrict__ out)
{
    const int b = blockIdx.z, h = blockIdx.y;
    const int row = blockIdx.x * 128 + threadIdx.x;
    __shared__ float4 Ks[32][16];
    __shared__ float4 Vs[32][16];
    float4 qr[16];
    {
        const float4* qp = reinterpret_cast<const float4*>(
            &q[((size_t)(b * NQ + row) * INNER) + h * DIMH]);
#pragma unroll
        for (int d = 0; d < 16; d++) qr[d] = qp[d];
    }
    float m = -INFINITY, l = 0.f;
    float4 acc[16];
#pragma unroll
    for (int d = 0; d < 16; d++) acc[d] = make_float4(0.f, 0.f, 0.f, 0.f);
    for (int kt = 0; kt < NK / 32; kt++) {
        __syncthreads();
#pragma unroll
        for (int t = 0; t < 4; t++) {
            const int e = threadIdx.x + t * 128;
            const int jrow = e >> 4, d4 = e & 15;
            const size_t gk = ((size_t)(b * NK + kt * 32 + jrow) * INNER) + h * DIMH;
            Ks[jrow][d4] = reinterpret_cast<const float4*>(&k[gk])[d4];
            Vs[jrow][d4] = reinterpret_cast<const float4*>(&v[gk])[d4];
        }
        __syncthreads();
        float s[32];
#pragma unroll
        for (int j = 0; j < 32; j++) {
            float a = 0.f;
#pragma unroll
            for (int d = 0; d < 16; d++) {
                const float4 kk = Ks[j][d];
                a += qr[d].x * kk.x + qr[d].y * kk.y + qr[d].z * kk.z + qr[d].w * kk.w;
            }
            s[j] = a * SCALE;
        }
        float tmax = s[0];
#pragma unroll
        for (int j = 1; j < 32; j++) tmax = fmaxf(tmax, s[j]);
        const float m_new = fmaxf(m, tmax);
        const float corr = __expf(m - m_new);
        l *= corr;
#pragma unroll
        for (int d = 0; d < 16; d++) {
            acc[d].x *= corr; acc[d].y *= corr; acc[d].z *= corr; acc[d].w *= corr;
        }
        m = m_new;
#pragma unroll
        for (int j = 0; j < 32; j++) {
            const float p = __expf(s[j] - m);
            l += p;
#pragma unroll
            for (int d = 0; d < 16; d++) {
                const float4 vv = Vs[j][d];
                acc[d].x += p * vv.x; acc[d].y += p * vv.y;
                acc[d].z += p * vv.z; acc[d].w += p * vv.w;
            }
        }
    }
    const float inv = 1.f / l;
    float4* op = reinterpret_cast<float4*>(&out[((size_t)(b * NQ + row) * INNER) + h * DIMH]);
#pragma unroll
    for (int d = 0; d < 16; d++)
        op[d] = make_float4(acc[d].x * inv, acc[d].y * inv, acc[d].z * inv, acc[d].w * inv);
}

// ------------------------------------------------------------
extern "C" void kernel_launch(void* const* d_in, const int* in_sizes, int n_in,
                              void* d_out, int out_size)
{
    const float* x   = (const float*)d_in[0];
    const float* ctx = (const float*)d_in[1];
    const float* Wq  = (const float*)d_in[2];
    const float* Wk  = (const float*)d_in[3];
    const float* Wv  = (const float*)d_in[4];
    const float* Wo  = (const float*)d_in[5];
    const float* bo  = (const float*)d_in[6];
    float* out       = (float*)d_out;

    float *q, *k, *v, *ao;
    __nv_bfloat16 *wh, *wl;
    cudaGetSymbolAddress((void**)&q,  g_q);
    cudaGetSymbolAddress((void**)&k,  g_k);
    cudaGetSymbolAddress((void**)&v,  g_v);
    cudaGetSymbolAddress((void**)&ao, g_ao);
    cudaGetSymbolAddress((void**)&wh, g_wth);
    cudaGetSymbolAddress((void**)&wl, g_wtl);

    cudaFuncSetAttribute(tc_gemm, cudaFuncAttributeMaxDynamicSharedMemorySize, TC_SMEM);

    transpose_split<<<dim3(DQ / 32, INNER / 32), 256>>>(Wq, wh + WT_Q, wl + WT_Q, DQ, INNER);
    transpose_split<<<dim3(DC / 32, INNER / 32), 256>>>(Wk, wh + WT_K, wl + WT_K, DC, INNER);
    transpose_split<<<dim3(DC / 32, INNER / 32), 256>>>(Wv, wh + WT_V, wl + WT_V, DC, INNER);
    transpose_split<<<dim3(INNER / 32, DQ / 32), 256>>>(Wo, wh + WT_O, wl + WT_O, INNER, DQ);

    tc_gemm<<<dim3(INNER / 128, (B_ * NQ) / 128), 256, TC_SMEM>>>(
        x, wh + WT_Q, wl + WT_Q, q, B_ * NQ, INNER, DQ, nullptr);
    tc_gemm<<<dim3(INNER / 128, (B_ * NK) / 128), 256, TC_SMEM>>>(
        ctx, wh + WT_K, wl + WT_K, k, B_ * NK, INNER, DC, nullptr);
    tc_gemm<<<dim3(INNER / 128, (B_ * NK) / 128), 256, TC_SMEM>>>(
        ctx, wh + WT_V, wl + WT_V, v, B_ * NK, INNER, DC, nullptr);

    attn_kernel<<<dim3(NQ / 128, HEADS, B_), 128>>>(q, k, v, ao);

    tc_gemm<<<dim3(DQ / 128, (B_ * NQ) / 128), 256, TC_SMEM>>>(
        ao, wh + WT_O, wl + WT_O, out, B_ * NQ, DQ, INNER, bo);
}

// round 9
// speedup vs baseline: 3.0421x; 2.2877x over previous
#include <cuda_runtime.h>
#include <cuda_bf16.h>
#include <math.h>
#include <stdint.h>

#define B_      4
#define NQ      2048
#define NK      1024
#define DQ      512
#define DC      768
#define HEADS   8
#define DIMH    64
#define INNER   512
#define SCALE   0.125f

__device__ float g_ao[B_ * NQ * INNER];
__device__ __nv_bfloat16 g_qh[B_ * NQ * INNER], g_ql[B_ * NQ * INNER];
__device__ __nv_bfloat16 g_kh[B_ * NK * INNER], g_kl[B_ * NK * INNER];
__device__ __nv_bfloat16 g_vh[B_ * NK * INNER], g_vl[B_ * NK * INNER];

#define WT_Q 0
#define WT_K (512*512)
#define WT_V (512*512 + 768*512)
#define WT_O (512*512 + 2*768*512)
#define WT_TOTAL (2*512*512 + 2*768*512)
__device__ __nv_bfloat16 g_wth[WT_TOTAL];
__device__ __nv_bfloat16 g_wtl[WT_TOTAL];

// ---------------- helpers ----------------
__device__ __forceinline__ uint32_t smem_u32(const void* p) {
    uint32_t a;
    asm("{ .reg .u64 t; cvta.to.shared.u64 t, %1; cvt.u32.u64 %0, t; }" : "=r"(a) : "l"(p));
    return a;
}
__device__ __forceinline__ uint32_t sw128(uint32_t o) { return o ^ ((o >> 3) & 0x70); }
__device__ __forceinline__ void ldsm_x4(uint32_t* r, uint32_t addr) {
    asm volatile("ldmatrix.sync.aligned.m8n8.x4.shared.b16 {%0,%1,%2,%3}, [%4];"
                 : "=r"(r[0]), "=r"(r[1]), "=r"(r[2]), "=r"(r[3]) : "r"(addr));
}
__device__ __forceinline__ void ldsm_x2(uint32_t* r, uint32_t addr) {
    asm volatile("ldmatrix.sync.aligned.m8n8.x2.shared.b16 {%0,%1}, [%2];"
                 : "=r"(r[0]), "=r"(r[1]) : "r"(addr));
}
__device__ __forceinline__ void ldsm_x2t(uint32_t* r, uint32_t addr) {
    asm volatile("ldmatrix.sync.aligned.m8n8.x2.trans.shared.b16 {%0,%1}, [%2];"
                 : "=r"(r[0]), "=r"(r[1]) : "r"(addr));
}
__device__ __forceinline__ void mma16816(float* c, const uint32_t* a, const uint32_t* b) {
    asm volatile("mma.sync.aligned.m16n8k16.row.col.f32.bf16.bf16.f32 "
                 "{%0,%1,%2,%3}, {%4,%5,%6,%7}, {%8,%9}, {%0,%1,%2,%3};"
                 : "+f"(c[0]), "+f"(c[1]), "+f"(c[2]), "+f"(c[3])
                 : "r"(a[0]), "r"(a[1]), "r"(a[2]), "r"(a[3]), "r"(b[0]), "r"(b[1]));
}
// split f32 -> (hi bf16 by truncation, lo bf16 rn of remainder), packed pair
__device__ __forceinline__ void split2(float x, float y, uint32_t& hi, uint32_t& lo) {
    uint32_t bx = __float_as_uint(x), by = __float_as_uint(y);
    hi = (bx >> 16) | (by & 0xFFFF0000u);
    __nv_bfloat162 l = __floats2bfloat162_rn(
        x - __uint_as_float(bx & 0xFFFF0000u), y - __uint_as_float(by & 0xFFFF0000u));
    lo = reinterpret_cast<uint32_t&>(l);
}

// ------------- weight transpose + split -------------
__global__ __launch_bounds__(256)
void transpose_split(const float* __restrict__ W, __nv_bfloat16* __restrict__ Th,
                     __nv_bfloat16* __restrict__ Tl, int K, int N)
{
    __shared__ float tile[32][33];
    const int k0 = blockIdx.x * 32, n0 = blockIdx.y * 32;
    const int tx = threadIdx.x & 31, ty = threadIdx.x >> 5;
#pragma unroll
    for (int r = 0; r < 4; r++)
        tile[ty + r * 8][tx] = W[(size_t)(k0 + ty + r * 8) * N + n0 + tx];
    __syncthreads();
#pragma unroll
    for (int r = 0; r < 4; r++) {
        int n = n0 + ty + r * 8, k = k0 + tx;
        float v = tile[tx][ty + r * 8];
        uint32_t b = __float_as_uint(v);
        unsigned short hs = (unsigned short)(b >> 16);
        float hi = __uint_as_float(b & 0xFFFF0000u);
        __nv_bfloat16 h; reinterpret_cast<unsigned short&>(h) = hs;
        Th[(size_t)n * K + k] = h;
        Tl[(size_t)n * K + k] = __float2bfloat16(v - hi);
    }
}

// ------------- HMMA split-bf16 GEMM -------------
// C = A[M,K] @ W[K,N]; out either f32 (Cf,+bias) or split bf16 (Chi/Clo), pre-scaled.
#define TC_SMEM 65536
#define AHI 0
#define ALO 16384
#define BHI 32768
#define BLO 49152

__global__ __launch_bounds__(256)
void tc_gemm(const float* __restrict__ A, const __nv_bfloat16* __restrict__ Bh,
             const __nv_bfloat16* __restrict__ Bl,
             float* __restrict__ Cf, __nv_bfloat16* __restrict__ Chi,
             __nv_bfloat16* __restrict__ Clo,
             int M, int N, int K, const float* __restrict__ bias, float scale)
{
    extern __shared__ char tb[];
    const uint32_t sbase = smem_u32(tb);
    const int tid = threadIdx.x, wid = tid >> 5, lane = tid & 31;
    const int m0 = blockIdx.y * 128, n0 = blockIdx.x * 128;
    const int wm = (wid & 3) * 32, wn = (wid >> 2) * 64;

    float acc[2][8][4];
#pragma unroll
    for (int mt = 0; mt < 2; mt++)
#pragma unroll
        for (int nt = 0; nt < 8; nt++)
#pragma unroll
            for (int i = 0; i < 4; i++) acc[mt][nt][i] = 0.f;

    const int r8 = lane & 7, q4 = lane >> 3, q2 = (lane & 15) >> 3;

    const int nchunks = K >> 6;
    for (int kt = 0; kt < nchunks; kt++) {
        const int kb = kt << 6;
#pragma unroll
        for (int t = 0; t < 8; t++) {
            int idx = tid + t * 256;
            int row = idx >> 4, c4 = (idx & 15) << 2;
            float4 v = *reinterpret_cast<const float4*>(&A[(size_t)(m0 + row) * K + kb + c4]);
            uint32_t h01, l01, h23, l23;
            split2(v.x, v.y, h01, l01);
            split2(v.z, v.w, h23, l23);
            uint32_t off = sw128((uint32_t)(row * 128 + (c4 << 1)));
            *reinterpret_cast<uint64_t*>(tb + AHI + off) = ((uint64_t)h23 << 32) | h01;
            *reinterpret_cast<uint64_t*>(tb + ALO + off) = ((uint64_t)l23 << 32) | l01;
        }
#pragma unroll
        for (int t = 0; t < 4; t++) {
            int idx = tid + t * 256;
            int row = idx >> 3, c8 = (idx & 7) << 3;
            size_t g = (size_t)(n0 + row) * K + kb + c8;
            uint32_t off = sw128((uint32_t)(row * 128 + (c8 << 1)));
            *reinterpret_cast<uint4*>(tb + BHI + off) = *reinterpret_cast<const uint4*>(&Bh[g]);
            *reinterpret_cast<uint4*>(tb + BLO + off) = *reinterpret_cast<const uint4*>(&Bl[g]);
        }
        __syncthreads();
#pragma unroll
        for (int ks = 0; ks < 4; ks++) {
            const int kk = ks * 16;
            uint32_t ah[2][4], al[2][4];
#pragma unroll
            for (int mt = 0; mt < 2; mt++) {
                int am = wm + mt * 16 + r8 + (q4 & 1) * 8;
                int ak = kk + (q4 >> 1) * 8;
                uint32_t o = sw128((uint32_t)(am * 128 + ak * 2));
                ldsm_x4(ah[mt], sbase + AHI + o);
                ldsm_x4(al[mt], sbase + ALO + o);
            }
#pragma unroll
            for (int nt = 0; nt < 8; nt++) {
                int bn = wn + nt * 8 + r8;
                int bk = kk + q2 * 8;
                uint32_t o = sw128((uint32_t)(bn * 128 + bk * 2));
                uint32_t bh[2], bl[2];
                ldsm_x2(bh, sbase + BHI + o);
                ldsm_x2(bl, sbase + BLO + o);
#pragma unroll
                for (int mt = 0; mt < 2; mt++) {
                    mma16816(acc[mt][nt], ah[mt], bh);
                    mma16816(acc[mt][nt], al[mt], bh);
                    mma16816(acc[mt][nt], ah[mt], bl);
                }
            }
        }
        __syncthreads();
    }

    const int cr = lane >> 2, cc = (lane & 3) * 2;
#pragma unroll
    for (int mt = 0; mt < 2; mt++) {
#pragma unroll
        for (int nt = 0; nt < 8; nt++) {
            int col = n0 + wn + nt * 8 + cc;
            int row = m0 + wm + mt * 16 + cr;
            float v0 = acc[mt][nt][0] * scale, v1 = acc[mt][nt][1] * scale;
            float v2 = acc[mt][nt][2] * scale, v3 = acc[mt][nt][3] * scale;
            if (Cf) {
                float b0 = 0.f, b1 = 0.f;
                if (bias) { b0 = bias[col]; b1 = bias[col + 1]; }
                *reinterpret_cast<float2*>(&Cf[(size_t)row * N + col]) = make_float2(v0 + b0, v1 + b1);
                *reinterpret_cast<float2*>(&Cf[(size_t)(row + 8) * N + col]) = make_float2(v2 + b0, v3 + b1);
            } else {
                uint32_t h01, l01, h23, l23;
                split2(v0, v1, h01, l01);
                split2(v2, v3, h23, l23);
                *reinterpret_cast<uint32_t*>(&Chi[(size_t)row * N + col]) = h01;
                *reinterpret_cast<uint32_t*>(&Clo[(size_t)row * N + col]) = l01;
                *reinterpret_cast<uint32_t*>(&Chi[(size_t)(row + 8) * N + col]) = h23;
                *reinterpret_cast<uint32_t*>(&Clo[(size_t)(row + 8) * N + col]) = l23;
            }
        }
    }
}

// ------------- tensor-core flash attention -------------
// block: 128 thr / 4 warps; 64 q-rows for one (b,h); 64-key tiles.
// smem: QH 0, QL 8K, KH 16K, KL 24K, VH 32K, VL 40K (rows = 128B SW128).
__global__ __launch_bounds__(128)
void attn_tc(const __nv_bfloat16* __restrict__ qh, const __nv_bfloat16* __restrict__ ql,
             const __nv_bfloat16* __restrict__ kh, const __nv_bfloat16* __restrict__ kl,
             const __nv_bfloat16* __restrict__ vh, const __nv_bfloat16* __restrict__ vl,
             float* __restrict__ out)
{
    __shared__ char sm[49152];
    const uint32_t sb = smem_u32(sm);
    const int b = blockIdx.z, h = blockIdx.y, q0 = blockIdx.x * 64;
    const int tid = threadIdx.x, wid = tid >> 5, lane = tid & 31;
    const int r8 = lane & 7, q4 = lane >> 3, q2 = (lane & 15) >> 3, l16 = lane & 15;

    // load Q tile (64 x 64 bf16, hi+lo)
#pragma unroll
    for (int t = 0; t < 4; t++) {
        int idx = tid + t * 128;                // 0..511
        int row = idx >> 3, c8 = (idx & 7) << 3;
        size_t g = ((size_t)(b * NQ + q0 + row) * INNER) + h * DIMH + c8;
        uint32_t off = sw128((uint32_t)(row * 128 + (c8 << 1)));
        *reinterpret_cast<uint4*>(sm + 0    + off) = *reinterpret_cast<const uint4*>(&qh[g]);
        *reinterpret_cast<uint4*>(sm + 8192 + off) = *reinterpret_cast<const uint4*>(&ql[g]);
    }
    __syncthreads();

    // q fragments (per warp: 16 rows)
    uint32_t qfh[4][4], qfl[4][4];
#pragma unroll
    for (int ks = 0; ks < 4; ks++) {
        int row = wid * 16 + r8 + (q4 & 1) * 8;
        int col = ks * 16 + (q4 >> 1) * 8;
        uint32_t off = sw128((uint32_t)(row * 128 + col * 2));
        ldsm_x4(qfh[ks], sb + 0 + off);
        ldsm_x4(qfl[ks], sb + 8192 + off);
    }

    float o[8][4];
#pragma unroll
    for (int nt = 0; nt < 8; nt++)
#pragma unroll
        for (int i = 0; i < 4; i++) o[nt][i] = 0.f;
    float m0 = -INFINITY, m1 = -INFINITY, L0 = 0.f, L1 = 0.f;

    for (int kt = 0; kt < NK / 64; kt++) {
        __syncthreads();
#pragma unroll
        for (int t = 0; t < 4; t++) {
            int idx = tid + t * 128;
            int row = idx >> 3, c8 = (idx & 7) << 3;
            size_t g = ((size_t)(b * NK + kt * 64 + row) * INNER) + h * DIMH + c8;
            uint32_t off = sw128((uint32_t)(row * 128 + (c8 << 1)));
            *reinterpret_cast<uint4*>(sm + 16384 + off) = *reinterpret_cast<const uint4*>(&kh[g]);
            *reinterpret_cast<uint4*>(sm + 24576 + off) = *reinterpret_cast<const uint4*>(&kl[g]);
            *reinterpret_cast<uint4*>(sm + 32768 + off) = *reinterpret_cast<const uint4*>(&vh[g]);
            *reinterpret_cast<uint4*>(sm + 40960 + off) = *reinterpret_cast<const uint4*>(&vl[g]);
        }
        __syncthreads();

        // S = Q K^T (scale pre-folded into Q)
        float s[8][4];
#pragma unroll
        for (int nt = 0; nt < 8; nt++)
#pragma unroll
            for (int i = 0; i < 4; i++) s[nt][i] = 0.f;
#pragma unroll
        for (int ks = 0; ks < 4; ks++) {
#pragma unroll
            for (int nt = 0; nt < 8; nt++) {
                uint32_t off = sw128((uint32_t)((nt * 8 + r8) * 128 + (ks * 16 + q2 * 8) * 2));
                uint32_t bh2[2], bl2[2];
                ldsm_x2(bh2, sb + 16384 + off);
                ldsm_x2(bl2, sb + 24576 + off);
                mma16816(s[nt], qfh[ks], bh2);
                mma16816(s[nt], qfl[ks], bh2);
                mma16816(s[nt], qfh[ks], bl2);
            }
        }

        // online softmax (rows: r = lane>>2 and r+8)
        float mx0 = -INFINITY, mx1 = -INFINITY;
#pragma unroll
        for (int nt = 0; nt < 8; nt++) {
            mx0 = fmaxf(mx0, fmaxf(s[nt][0], s[nt][1]));
            mx1 = fmaxf(mx1, fmaxf(s[nt][2], s[nt][3]));
        }
        mx0 = fmaxf(mx0, __shfl_xor_sync(0xFFFFFFFFu, mx0, 1));
        mx0 = fmaxf(mx0, __shfl_xor_sync(0xFFFFFFFFu, mx0, 2));
        mx1 = fmaxf(mx1, __shfl_xor_sync(0xFFFFFFFFu, mx1, 1));
        mx1 = fmaxf(mx1, __shfl_xor_sync(0xFFFFFFFFu, mx1, 2));
        float mn0 = fmaxf(m0, mx0), mn1 = fmaxf(m1, mx1);
        float c0 = __expf(m0 - mn0), c1 = __expf(m1 - mn1);
        m0 = mn0; m1 = mn1;
        L0 *= c0; L1 *= c1;
#pragma unroll
        for (int nt = 0; nt < 8; nt++) {
            o[nt][0] *= c0; o[nt][1] *= c0; o[nt][2] *= c1; o[nt][3] *= c1;
        }

        // P = exp(S - m), split to bf16 hi/lo A-fragments
        uint32_t pha[8], phb[8], pla[8], plb[8];
#pragma unroll
        for (int nt = 0; nt < 8; nt++) {
            float p0 = __expf(s[nt][0] - m0), p1 = __expf(s[nt][1] - m0);
            float p2 = __expf(s[nt][2] - m1), p3 = __expf(s[nt][3] - m1);
            L0 += p0 + p1; L1 += p2 + p3;
            split2(p0, p1, pha[nt], pla[nt]);
            split2(p2, p3, phb[nt], plb[nt]);
        }

        // O += P V   (V^T via ldmatrix.trans)
#pragma unroll
        for (int ks2 = 0; ks2 < 4; ks2++) {
            uint32_t ah[4] = { pha[2 * ks2], phb[2 * ks2], pha[2 * ks2 + 1], phb[2 * ks2 + 1] };
            uint32_t al[4] = { pla[2 * ks2], plb[2 * ks2], pla[2 * ks2 + 1], plb[2 * ks2 + 1] };
#pragma unroll
            for (int nt = 0; nt < 8; nt++) {
                uint32_t off = sw128((uint32_t)((ks2 * 16 + l16) * 128 + nt * 16));
                uint32_t vbh[2], vbl[2];
                ldsm_x2t(vbh, sb + 32768 + off);
                ldsm_x2t(vbl, sb + 40960 + off);
                mma16816(o[nt], ah, vbh);
                mma16816(o[nt], al, vbh);
                mma16816(o[nt], ah, vbl);
            }
        }
    }

    L0 += __shfl_xor_sync(0xFFFFFFFFu, L0, 1);
    L0 += __shfl_xor_sync(0xFFFFFFFFu, L0, 2);
    L1 += __shfl_xor_sync(0xFFFFFFFFu, L1, 1);
    L1 += __shfl_xor_sync(0xFFFFFFFFu, L1, 2);
    const float inv0 = 1.f / L0, inv1 = 1.f / L1;
    const int row0 = q0 + wid * 16 + (lane >> 2);
#pragma unroll
    for (int nt = 0; nt < 8; nt++) {
        int col = h * DIMH + nt * 8 + 2 * (lane & 3);
        size_t g0 = ((size_t)(b * NQ + row0) * INNER) + col;
        size_t g1 = ((size_t)(b * NQ + row0 + 8) * INNER) + col;
        *reinterpret_cast<float2*>(&out[g0]) = make_float2(o[nt][0] * inv0, o[nt][1] * inv0);
        *reinterpret_cast<float2*>(&out[g1]) = make_float2(o[nt][2] * inv1, o[nt][3] * inv1);
    }
}

// ------------------------------------------------------------
extern "C" void kernel_launch(void* const* d_in, const int* in_sizes, int n_in,
                              void* d_out, int out_size)
{
    const float* x   = (const float*)d_in[0];
    const float* ctx = (const float*)d_in[1];
    const float* Wq  = (const float*)d_in[2];
    const float* Wk  = (const float*)d_in[3];
    const float* Wv  = (const float*)d_in[4];
    const float* Wo  = (const float*)d_in[5];
    const float* bo  = (const float*)d_in[6];
    float* out       = (float*)d_out;

    float* ao;
    __nv_bfloat16 *wh, *wl, *qh, *ql, *kh, *kl, *vh, *vl;
    cudaGetSymbolAddress((void**)&ao, g_ao);
    cudaGetSymbolAddress((void**)&wh, g_wth);
    cudaGetSymbolAddress((void**)&wl, g_wtl);
    cudaGetSymbolAddress((void**)&qh, g_qh);
    cudaGetSymbolAddress((void**)&ql, g_ql);
    cudaGetSymbolAddress((void**)&kh, g_kh);
    cudaGetSymbolAddress((void**)&kl, g_kl);
    cudaGetSymbolAddress((void**)&vh, g_vh);
    cudaGetSymbolAddress((void**)&vl, g_vl);

    cudaFuncSetAttribute(tc_gemm, cudaFuncAttributeMaxDynamicSharedMemorySize, TC_SMEM);

    transpose_split<<<dim3(DQ / 32, INNER / 32), 256>>>(Wq, wh + WT_Q, wl + WT_Q, DQ, INNER);
    transpose_split<<<dim3(DC / 32, INNER / 32), 256>>>(Wk, wh + WT_K, wl + WT_K, DC, INNER);
    transpose_split<<<dim3(DC / 32, INNER / 32), 256>>>(Wv, wh + WT_V, wl + WT_V, DC, INNER);
    transpose_split<<<dim3(INNER / 32, DQ / 32), 256>>>(Wo, wh + WT_O, wl + WT_O, INNER, DQ);

    tc_gemm<<<dim3(INNER / 128, (B_ * NQ) / 128), 256, TC_SMEM>>>(
        x, wh + WT_Q, wl + WT_Q, nullptr, qh, ql, B_ * NQ, INNER, DQ, nullptr, SCALE);
    tc_gemm<<<dim3(INNER / 128, (B_ * NK) / 128), 256, TC_SMEM>>>(
        ctx, wh + WT_K, wl + WT_K, nullptr, kh, kl, B_ * NK, INNER, DC, nullptr, 1.0f);
    tc_gemm<<<dim3(INNER / 128, (B_ * NK) / 128), 256, TC_SMEM>>>(
        ctx, wh + WT_V, wl + WT_V, nullptr, vh, vl, B_ * NK, INNER, DC, nullptr, 1.0f);

    attn_tc<<<dim3(NQ / 64, HEADS, B_), 128>>>(qh, ql, kh, kl, vh, vl, ao);

    tc_gemm<<<dim3(DQ / 128, (B_ * NQ) / 128), 256, TC_SMEM>>>(
        ao, wh + WT_O, wl + WT_O, out, nullptr, nullptr, B_ * NQ, DQ, INNER, bo, 1.0f);
}